// round 13
// baseline (speedup 1.0000x reference)
#include <cuda_runtime.h>
#include <cuda_fp16.h>
#include <math.h>
#include <stdint.h>

#define N_NODES 50000
#define N_PAD   50176          // 392 * 128
#define N_EDGES 600000
#define IN_DIM  128
#define HID_DIM 512
#define N_MTILES 392
#define GX_CTAS 1568           // 196 m-tiles * 8 n-blocks per half

// ---------------- scratch ----------------------------------------------------
__device__ int   g_cnt[N_NODES];          // zero-init; final_kernel re-zeroes
__device__ int   g_bsum[64];
__device__ int   g_row[N_NODES + 1];
__device__ int   g_cursor[N_NODES];
__device__ int   g_csr[N_EDGES];
__device__ float g_invd[N_NODES];
__device__ __align__(16) __half g_xh  [N_PAD * IN_DIM];
__device__ __align__(16) __half g_aggh[N_PAD * IN_DIM];
__device__ __align__(16) __half g_Wh  [256 * HID_DIM];    // [k][n]: k<128 W1l else W1r
__device__ __align__(16) __half g_hparth[(long long)N_PAD * HID_DIM];  // x @ W1r (f16)
__device__ float g_pq[N_NODES * 4];

__device__ __forceinline__ uint32_t packh2(float a, float b) {
    __half2 h = __floats2half2_rn(a, b);
    return *reinterpret_cast<uint32_t*>(&h);
}

// ---------------- 0. prep: zero pq + convert x/W + histogram -------------------
__global__ void prep_kernel(const float* __restrict__ x,
                            const float* __restrict__ W1l,
                            const float* __restrict__ W1r,
                            const int* __restrict__ edge_index) {
    int i = blockIdx.x * blockDim.x + threadIdx.x;
    if (i < N_NODES * 4) g_pq[i] = 0.f;
    if (i < N_EDGES) atomicAdd(&g_cnt[edge_index[N_EDGES + i]], 1);
    const int xtot = N_PAD * IN_DIM / 8;
    if (i < xtot) {
        long long base = (long long)i * 8;
        int m = (int)(base / IN_DIM);
        uint4 o;
        if (m < N_NODES) {
            float4 v0 = *reinterpret_cast<const float4*>(x + base);
            float4 v1 = *reinterpret_cast<const float4*>(x + base + 4);
            o.x = packh2(v0.x, v0.y); o.y = packh2(v0.z, v0.w);
            o.z = packh2(v1.x, v1.y); o.w = packh2(v1.z, v1.w);
        } else o = make_uint4(0, 0, 0, 0);
        *reinterpret_cast<uint4*>(g_xh + base) = o;
    }
    const int wtot = 256 * HID_DIM / 4;
    if (i < wtot) {
        int base = i * 4;
        int k = base >> 9;
        int n = base & 511;
        const float* W = (k < IN_DIM) ? (W1l + k * HID_DIM + n)
                                      : (W1r + (k - IN_DIM) * HID_DIM + n);
        float4 v = *reinterpret_cast<const float4*>(W);
        uint2 o; o.x = packh2(v.x, v.y); o.y = packh2(v.z, v.w);
        *reinterpret_cast<uint2*>(g_Wh + base) = o;
    }
}

// ---------------- 1. scan phase 1 ------------------------------------------------
__global__ void scan1_kernel() {
    __shared__ int sm[1024];
    const int b = blockIdx.x, t = threadIdx.x;
    const int i = b * 1024 + t;
    int c = (i < N_NODES) ? g_cnt[i] : 0;
    sm[t] = c;
    __syncthreads();
    for (int off = 1; off < 1024; off <<= 1) {
        int u = (t >= off) ? sm[t - off] : 0;
        __syncthreads();
        sm[t] += u;
        __syncthreads();
    }
    int incl = sm[t];
    if (i < N_NODES) g_row[i] = incl - c;
    if (t == 1023) g_bsum[b] = incl;
}

// ---------------- 2. scan phase 2 ------------------------------------------------
__global__ void scan2_kernel() {
    __shared__ int bs[64];
    const int b = blockIdx.x, t = threadIdx.x;
    if (t < 49) bs[t] = g_bsum[t];
    __syncthreads();
    int boff = 0;
    for (int j = 0; j < b; j++) boff += bs[j];
    const int i = b * 1024 + t;
    if (i < N_NODES) {
        int row = g_row[i] + boff;
        g_row[i] = row;
        g_cursor[i] = row;
        g_invd[i] = 1.f / fmaxf((float)g_cnt[i], 1.f);
    }
    if (b == 0 && t == 0) g_row[N_NODES] = N_EDGES;
}

// ---------------- mma helpers ----------------------------------------------------
__device__ __forceinline__ void ldsm_x4(uint32_t* r, uint32_t addr) {
    asm volatile("ldmatrix.sync.aligned.m8n8.x4.shared.b16 {%0,%1,%2,%3}, [%4];"
                 : "=r"(r[0]), "=r"(r[1]), "=r"(r[2]), "=r"(r[3]) : "r"(addr));
}
__device__ __forceinline__ void ldsm_x4t(uint32_t* r, uint32_t addr) {
    asm volatile("ldmatrix.sync.aligned.m8n8.x4.trans.shared.b16 {%0,%1,%2,%3}, [%4];"
                 : "=r"(r[0]), "=r"(r[1]), "=r"(r[2]), "=r"(r[3]) : "r"(addr));
}
__device__ __forceinline__ void mma_f16(float* d, const uint32_t* a, const uint32_t* b) {
    asm volatile(
        "mma.sync.aligned.m16n8k16.row.col.f32.f16.f16.f32 "
        "{%0,%1,%2,%3}, {%4,%5,%6,%7}, {%8,%9}, {%0,%1,%2,%3};"
        : "+f"(d[0]), "+f"(d[1]), "+f"(d[2]), "+f"(d[3])
        : "r"(a[0]), "r"(a[1]), "r"(a[2]), "r"(a[3]), "r"(b[0]), "r"(b[1]));
}
__device__ __forceinline__ void cp16(uint32_t smem_addr, const void* gptr) {
    asm volatile("cp.async.cg.shared.global [%0], [%1], 16;"
                 :: "r"(smem_addr), "l"(gptr) : "memory");
}

// ---------------- tile config: BM=128, BN=64, K=128 resident, 4 CTAs/SM ----------
#define SA 136                            // A row stride (halfs): 128+8
#define SB 72                             // B row stride (halfs): 64+8
#define GX_A 0
#define GX_B (128 * SA * 2)               // 34816
#define GX_SMEM (GX_B + 128 * SB * 2)     // 34816 + 18432 = 53248
#define GA_WC GX_SMEM
#define GA_BIAS (GA_WC + 64 * 4 * 4)      // +1024
#define GA_SMEM (GA_BIAS + 64 * 4)        // 54528

// ---------------- gemm_x tile: hparth[mt, nb] = x_tile @ W1r_tile (f16 out) ------
// warp grid 2x4, warp tile 64x16; 2-phase k-chunk pipeline
__device__ __forceinline__ void gemmx_tile(int mt, int nb, char* smem, int tid) {
    const uint32_t sm_base = (uint32_t)__cvta_generic_to_shared(smem);
    const uint32_t as_u = sm_base + GX_A;
    const uint32_t bs_u = sm_base + GX_B;
    const int warp = tid >> 5, lane = tid & 31;
    const int wm = warp >> 2, wn = warp & 3;
    const int g8 = lane >> 2, t = lane & 3;
    const int block_m = mt * 128, block_n = nb * 64;

    #pragma unroll
    for (int ph = 0; ph < 2; ph++) {
        const int kb = ph * 64;
        #pragma unroll
        for (int i = 0; i < 4; i++) {
            int id = tid + i * 256;      // 0..1023
            int row = id >> 3;           // 0..127
            int ch = (id & 7) * 8;       // 0..56
            cp16(as_u + (row * SA + kb + ch) * 2,
                 g_xh + (long long)(block_m + row) * IN_DIM + kb + ch);
        }
        #pragma unroll
        for (int i = 0; i < 2; i++) {
            int id = tid + i * 256;      // 0..511
            int k = id >> 3;             // 0..63
            int nc = (id & 7) * 8;       // 0..56
            cp16(bs_u + ((kb + k) * SB + nc) * 2,
                 g_Wh + (128 + kb + k) * HID_DIM + block_n + nc);
        }
        asm volatile("cp.async.commit_group;" ::: "memory");
    }

    const uint32_t a_lane = ((wm * 64 + (lane & 15)) * SA + (lane >> 4) * 8) * 2;
    const uint32_t b_lane = ((lane & 15) * SB + (lane >> 4) * 8) * 2;

    float acc[4][2][4] = {};
    #pragma unroll
    for (int ph = 0; ph < 2; ph++) {
        if (ph == 0) asm volatile("cp.async.wait_group 1;" ::: "memory");
        else         asm volatile("cp.async.wait_group 0;" ::: "memory");
        __syncthreads();
        #pragma unroll
        for (int ks = 0; ks < 4; ks++) {
            const int kk = ph * 64 + ks * 16;
            uint32_t af[4][4], bf[2][2];
            #pragma unroll
            for (int mi = 0; mi < 4; mi++)
                ldsm_x4(af[mi], as_u + a_lane + (mi * 16 * SA + kk) * 2);
            {
                uint32_t r[4];
                ldsm_x4t(r, bs_u + b_lane + (kk * SB + wn * 16) * 2);
                bf[0][0] = r[0]; bf[0][1] = r[1];
                bf[1][0] = r[2]; bf[1][1] = r[3];
            }
            #pragma unroll
            for (int mi = 0; mi < 4; mi++)
                #pragma unroll
                for (int ni = 0; ni < 2; ni++)
                    mma_f16(acc[mi][ni], af[mi], bf[ni]);
        }
    }

    #pragma unroll
    for (int mi = 0; mi < 4; mi++) {
        #pragma unroll
        for (int half = 0; half < 2; half++) {
            const int m = block_m + wm * 64 + mi * 16 + g8 + half * 8;
            #pragma unroll
            for (int ni = 0; ni < 2; ni++) {
                const int n0 = block_n + wn * 16 + ni * 8 + 2 * t;
                uint32_t v = packh2(acc[mi][ni][half * 2 + 0],
                                    acc[mi][ni][half * 2 + 1]);
                *reinterpret_cast<uint32_t*>(g_hparth + (long long)m * HID_DIM + n0) = v;
            }
        }
    }
}

// ---------------- 3. K3: gemm_x half 0 + reorder ---------------------------------
__global__ __launch_bounds__(256, 4)
void k3_kernel(const int* __restrict__ edge_index) {
    extern __shared__ __align__(16) char smem[];
    if (blockIdx.x < GX_CTAS) {
        gemmx_tile((int)(blockIdx.x >> 3), (int)(blockIdx.x & 7), smem, threadIdx.x);
        return;
    }
    int id = (blockIdx.x - GX_CTAS) * 256 + threadIdx.x;
    int e0 = id * 2;
    if (e0 >= N_EDGES) return;
    int e1 = e0 + 1;
    int src0 = edge_index[e0];
    int dst0 = edge_index[N_EDGES + e0];
    int src1 = 0, dst1 = 0;
    bool has1 = (e1 < N_EDGES);
    if (has1) { src1 = edge_index[e1]; dst1 = edge_index[N_EDGES + e1]; }
    int p0 = atomicAdd(&g_cursor[dst0], 1);
    int p1 = has1 ? atomicAdd(&g_cursor[dst1], 1) : 0;
    g_csr[p0] = src0;
    if (has1) g_csr[p1] = src1;
}

// ---------------- 4. K4: gemm_x half 1 + gather-mean aggregation -----------------
__global__ __launch_bounds__(256, 4)
void k4_kernel() {
    extern __shared__ __align__(16) char smem[];
    if (blockIdx.x < GX_CTAS) {
        gemmx_tile(196 + (int)(blockIdx.x >> 3), (int)(blockIdx.x & 7), smem, threadIdx.x);
        return;
    }
    int id = (blockIdx.x - GX_CTAS) * 256 + threadIdx.x;
    int node = id >> 4;
    int l16 = id & 15;
    if (node >= N_PAD) return;
    float s[8] = {};
    if (node < N_NODES) {
        const int beg = g_row[node];
        const int end = g_row[node + 1];
        int e = beg;
        for (; e + 3 < end; e += 4) {
            int i0 = g_csr[e], i1 = g_csr[e + 1], i2 = g_csr[e + 2], i3 = g_csr[e + 3];
            uint4 v0 = *reinterpret_cast<const uint4*>(g_xh + (long long)i0 * IN_DIM + l16 * 8);
            uint4 v1 = *reinterpret_cast<const uint4*>(g_xh + (long long)i1 * IN_DIM + l16 * 8);
            uint4 v2 = *reinterpret_cast<const uint4*>(g_xh + (long long)i2 * IN_DIM + l16 * 8);
            uint4 v3 = *reinterpret_cast<const uint4*>(g_xh + (long long)i3 * IN_DIM + l16 * 8);
            const __half2* h0 = reinterpret_cast<const __half2*>(&v0);
            const __half2* h1 = reinterpret_cast<const __half2*>(&v1);
            const __half2* h2 = reinterpret_cast<const __half2*>(&v2);
            const __half2* h3 = reinterpret_cast<const __half2*>(&v3);
            #pragma unroll
            for (int j = 0; j < 4; j++) {
                float2 f0 = __half22float2(h0[j]);
                float2 f1 = __half22float2(h1[j]);
                float2 f2 = __half22float2(h2[j]);
                float2 f3 = __half22float2(h3[j]);
                s[j * 2 + 0] += (f0.x + f1.x) + (f2.x + f3.x);
                s[j * 2 + 1] += (f0.y + f1.y) + (f2.y + f3.y);
            }
        }
        for (; e < end; e++) {
            int i0 = g_csr[e];
            uint4 v0 = *reinterpret_cast<const uint4*>(g_xh + (long long)i0 * IN_DIM + l16 * 8);
            const __half2* h0 = reinterpret_cast<const __half2*>(&v0);
            #pragma unroll
            for (int j = 0; j < 4; j++) {
                float2 f0 = __half22float2(h0[j]);
                s[j * 2 + 0] += f0.x;
                s[j * 2 + 1] += f0.y;
            }
        }
        const float invd = g_invd[node];
        #pragma unroll
        for (int j = 0; j < 8; j++) s[j] *= invd;
    }
    uint4 o;
    o.x = packh2(s[0], s[1]); o.y = packh2(s[2], s[3]);
    o.z = packh2(s[4], s[5]); o.w = packh2(s[6], s[7]);
    *reinterpret_cast<uint4*>(g_aggh + (long long)node * IN_DIM + l16 * 8) = o;
}

// ---------------- 5. gemm_agg: agg@W1l + hparth, relu, project, accumulate -------
__global__ __launch_bounds__(256, 4)
void gemm_agg_kernel(const float* __restrict__ b1,
                     const float* __restrict__ W2l,
                     const float* __restrict__ W2r) {
    extern __shared__ __align__(16) char smem[];
    float (*Wc)[4] = reinterpret_cast<float(*)[4]>(smem + GA_WC);
    float* bias_s = reinterpret_cast<float*>(smem + GA_BIAS);

    const uint32_t sm_base = (uint32_t)__cvta_generic_to_shared(smem);
    const uint32_t as_u = sm_base + GX_A;
    const uint32_t bs_u = sm_base + GX_B;
    const int tid = threadIdx.x;
    const int warp = tid >> 5, lane = tid & 31;
    const int wm = warp >> 2, wn = warp & 3;
    const int g8 = lane >> 2, t = lane & 3;
    const int block_m = blockIdx.y * 128;
    const int block_n = blockIdx.x * 64;

    #pragma unroll
    for (int ph = 0; ph < 2; ph++) {
        const int kb = ph * 64;
        #pragma unroll
        for (int i = 0; i < 4; i++) {
            int id = tid + i * 256;
            int row = id >> 3;
            int ch = (id & 7) * 8;
            cp16(as_u + (row * SA + kb + ch) * 2,
                 g_aggh + (long long)(block_m + row) * IN_DIM + kb + ch);
        }
        #pragma unroll
        for (int i = 0; i < 2; i++) {
            int id = tid + i * 256;
            int k = id >> 3;
            int nc = (id & 7) * 8;
            cp16(bs_u + ((kb + k) * SB + nc) * 2,
                 g_Wh + (kb + k) * HID_DIM + block_n + nc);
        }
        asm volatile("cp.async.commit_group;" ::: "memory");
    }

    for (int idx = tid; idx < 64 * 4; idx += 256) {
        int nn = idx >> 2, c = idx & 3;
        int n = block_n + nn;
        Wc[nn][c] = (c < 2) ? W2l[n * 2 + c] : W2r[n * 2 + (c - 2)];
    }
    if (tid < 64) bias_s[tid] = b1[block_n + tid];

    const uint32_t a_lane = ((wm * 64 + (lane & 15)) * SA + (lane >> 4) * 8) * 2;
    const uint32_t b_lane = ((lane & 15) * SB + (lane >> 4) * 8) * 2;

    float acc[4][2][4] = {};
    #pragma unroll
    for (int ph = 0; ph < 2; ph++) {
        if (ph == 0) asm volatile("cp.async.wait_group 1;" ::: "memory");
        else         asm volatile("cp.async.wait_group 0;" ::: "memory");
        __syncthreads();
        #pragma unroll
        for (int ks = 0; ks < 4; ks++) {
            const int kk = ph * 64 + ks * 16;
            uint32_t af[4][4], bf[2][2];
            #pragma unroll
            for (int mi = 0; mi < 4; mi++)
                ldsm_x4(af[mi], as_u + a_lane + (mi * 16 * SA + kk) * 2);
            {
                uint32_t r[4];
                ldsm_x4t(r, bs_u + b_lane + (kk * SB + wn * 16) * 2);
                bf[0][0] = r[0]; bf[0][1] = r[1];
                bf[1][0] = r[2]; bf[1][1] = r[3];
            }
            #pragma unroll
            for (int mi = 0; mi < 4; mi++)
                #pragma unroll
                for (int ni = 0; ni < 2; ni++)
                    mma_f16(acc[mi][ni], af[mi], bf[ni]);
        }
    }

    // epilogue: + hparth + bias, relu, project, reduce over t-quad, accumulate
    #pragma unroll
    for (int mi = 0; mi < 4; mi++) {
        #pragma unroll
        for (int half = 0; half < 2; half++) {
            const int m = block_m + wm * 64 + mi * 16 + g8 + half * 8;
            float s0 = 0.f, s1 = 0.f, s2 = 0.f, s3 = 0.f;
            #pragma unroll
            for (int ni = 0; ni < 2; ni++) {
                const int nl = wn * 16 + ni * 8 + 2 * t;
                __half2 hh = *reinterpret_cast<const __half2*>(
                    g_hparth + (long long)m * HID_DIM + block_n + nl);
                float2 hp = __half22float2(hh);
                #pragma unroll
                for (int r = 0; r < 2; r++) {
                    float hpv = (r == 0) ? hp.x : hp.y;
                    float hv = fmaxf(acc[mi][ni][half * 2 + r] + hpv + bias_s[nl + r], 0.f);
                    s0 += hv * Wc[nl + r][0];
                    s1 += hv * Wc[nl + r][1];
                    s2 += hv * Wc[nl + r][2];
                    s3 += hv * Wc[nl + r][3];
                }
            }
            #pragma unroll
            for (int off = 1; off <= 2; off <<= 1) {
                s0 += __shfl_xor_sync(0xffffffff, s0, off);
                s1 += __shfl_xor_sync(0xffffffff, s1, off);
                s2 += __shfl_xor_sync(0xffffffff, s2, off);
                s3 += __shfl_xor_sync(0xffffffff, s3, off);
            }
            if (t == 0 && m < N_NODES) {
                atomicAdd(&g_pq[m * 4 + 0], s0);
                atomicAdd(&g_pq[m * 4 + 1], s1);
                atomicAdd(&g_pq[m * 4 + 2], s2);
                atomicAdd(&g_pq[m * 4 + 3], s3);
            }
        }
    }
}

// ---------------- 6. final: gather + log_softmax + reset g_cnt -------------------
__global__ void final_kernel(const float* __restrict__ b2,
                             float* __restrict__ out) {
    int n = blockIdx.x * blockDim.x + threadIdx.x;
    if (n >= N_NODES) return;
    g_cnt[n] = 0;
    const int beg = g_row[n];
    const int end = g_row[n + 1];
    float s0 = 0.f, s1 = 0.f;
    int e = beg;
    for (; e + 1 < end; e += 2) {
        int u = g_csr[e], v = g_csr[e + 1];
        float2 pu = *reinterpret_cast<const float2*>(&g_pq[u * 4]);
        float2 pv = *reinterpret_cast<const float2*>(&g_pq[v * 4]);
        s0 += pu.x + pv.x; s1 += pu.y + pv.y;
    }
    if (e < end) {
        int u = g_csr[e];
        float2 pu = *reinterpret_cast<const float2*>(&g_pq[u * 4]);
        s0 += pu.x; s1 += pu.y;
    }
    const float invd = g_invd[n];
    float o0 = s0 * invd + b2[0] + g_pq[n * 4 + 2];
    float o1 = s1 * invd + b2[1] + g_pq[n * 4 + 3];
    float m = fmaxf(o0, o1);
    float lse = m + logf(expf(o0 - m) + expf(o1 - m));
    out[n * 2 + 0] = o0 - lse;
    out[n * 2 + 1] = o1 - lse;
}

// ---------------- launcher ---------------------------------------------------------
extern "C" void kernel_launch(void* const* d_in, const int* in_sizes, int n_in,
                              void* d_out, int out_size) {
    const float* x    = (const float*)d_in[0];
    const float* W1l  = (const float*)d_in[1];
    const float* b1   = (const float*)d_in[2];
    const float* W1r  = (const float*)d_in[3];
    const float* W2l  = (const float*)d_in[4];
    const float* b2   = (const float*)d_in[5];
    const float* W2r  = (const float*)d_in[6];
    const int*   ei   = (const int*)d_in[7];
    float* out = (float*)d_out;

    cudaFuncSetAttribute(k3_kernel,
                         cudaFuncAttributeMaxDynamicSharedMemorySize, GX_SMEM);
    cudaFuncSetAttribute(k4_kernel,
                         cudaFuncAttributeMaxDynamicSharedMemorySize, GX_SMEM);
    cudaFuncSetAttribute(gemm_agg_kernel,
                         cudaFuncAttributeMaxDynamicSharedMemorySize, GA_SMEM);

    int prep_threads = N_PAD * IN_DIM / 8;
    prep_kernel<<<(prep_threads + 255) / 256, 256>>>(x, W1l, W1r, ei);
    scan1_kernel<<<49, 1024>>>();
    scan2_kernel<<<49, 1024>>>();

    {   // gemm_x half 0 + reorder
        int reorder_blocks = (N_EDGES / 2 + 255) / 256;          // 1172
        k3_kernel<<<GX_CTAS + reorder_blocks, 256, GX_SMEM>>>(ei);
    }
    {   // gemm_x half 1 + aggregate
        int agg_blocks = (N_PAD * 16) / 256;                      // 3136
        k4_kernel<<<GX_CTAS + agg_blocks, 256, GX_SMEM>>>();
    }
    {
        dim3 grid(HID_DIM / 64, N_MTILES);
        gemm_agg_kernel<<<grid, 256, GA_SMEM>>>(b1, W2l, W2r);
    }
    final_kernel<<<(N_NODES + 255) / 256, 256>>>(b2, out);
}

// round 14
// speedup vs baseline: 1.1957x; 1.1957x over previous
#include <cuda_runtime.h>
#include <cuda_fp16.h>
#include <math.h>
#include <stdint.h>

#define N_NODES 50000
#define N_PAD   50176          // 392 * 128
#define N_EDGES 600000
#define IN_DIM  128
#define HID_DIM 512
#define N_MTILES 392
#define GX_CTAS 392            // 98 m-tile PAIRS * 4 n-blocks per half

// ---------------- scratch ----------------------------------------------------
__device__ int   g_cnt[N_NODES];          // zero-init; final_kernel re-zeroes
__device__ int   g_bsum[64];
__device__ int   g_row[N_NODES + 1];
__device__ int   g_cursor[N_NODES];
__device__ int   g_csr[N_EDGES];
__device__ float g_invd[N_NODES];
__device__ __align__(16) __half g_xh  [N_PAD * IN_DIM];
__device__ __align__(16) __half g_aggh[N_PAD * IN_DIM];
__device__ __align__(16) __half g_Wh  [256 * HID_DIM];    // [k][n]: k<128 W1l else W1r
__device__ __align__(16) __half g_hparth[(long long)N_PAD * HID_DIM];  // x @ W1r (f16)
__device__ float g_pq[N_NODES * 4];

__device__ __forceinline__ uint32_t packh2(float a, float b) {
    __half2 h = __floats2half2_rn(a, b);
    return *reinterpret_cast<uint32_t*>(&h);
}

// ---------------- 0. prep: zero pq + convert x/W + histogram -------------------
__global__ void prep_kernel(const float* __restrict__ x,
                            const float* __restrict__ W1l,
                            const float* __restrict__ W1r,
                            const int* __restrict__ edge_index) {
    int i = blockIdx.x * blockDim.x + threadIdx.x;
    if (i < N_NODES * 4) g_pq[i] = 0.f;
    if (i < N_EDGES) atomicAdd(&g_cnt[edge_index[N_EDGES + i]], 1);
    const int xtot = N_PAD * IN_DIM / 8;
    if (i < xtot) {
        long long base = (long long)i * 8;
        int m = (int)(base / IN_DIM);
        uint4 o;
        if (m < N_NODES) {
            float4 v0 = *reinterpret_cast<const float4*>(x + base);
            float4 v1 = *reinterpret_cast<const float4*>(x + base + 4);
            o.x = packh2(v0.x, v0.y); o.y = packh2(v0.z, v0.w);
            o.z = packh2(v1.x, v1.y); o.w = packh2(v1.z, v1.w);
        } else o = make_uint4(0, 0, 0, 0);
        *reinterpret_cast<uint4*>(g_xh + base) = o;
    }
    const int wtot = 256 * HID_DIM / 4;
    if (i < wtot) {
        int base = i * 4;
        int k = base >> 9;
        int n = base & 511;
        const float* W = (k < IN_DIM) ? (W1l + k * HID_DIM + n)
                                      : (W1r + (k - IN_DIM) * HID_DIM + n);
        float4 v = *reinterpret_cast<const float4*>(W);
        uint2 o; o.x = packh2(v.x, v.y); o.y = packh2(v.z, v.w);
        *reinterpret_cast<uint2*>(g_Wh + base) = o;
    }
}

// ---------------- 1. scan phase 1 ------------------------------------------------
__global__ void scan1_kernel() {
    __shared__ int sm[1024];
    const int b = blockIdx.x, t = threadIdx.x;
    const int i = b * 1024 + t;
    int c = (i < N_NODES) ? g_cnt[i] : 0;
    sm[t] = c;
    __syncthreads();
    for (int off = 1; off < 1024; off <<= 1) {
        int u = (t >= off) ? sm[t - off] : 0;
        __syncthreads();
        sm[t] += u;
        __syncthreads();
    }
    int incl = sm[t];
    if (i < N_NODES) g_row[i] = incl - c;
    if (t == 1023) g_bsum[b] = incl;
}

// ---------------- 2. scan phase 2 ------------------------------------------------
__global__ void scan2_kernel() {
    __shared__ int bs[64];
    const int b = blockIdx.x, t = threadIdx.x;
    if (t < 49) bs[t] = g_bsum[t];
    __syncthreads();
    int boff = 0;
    for (int j = 0; j < b; j++) boff += bs[j];
    const int i = b * 1024 + t;
    if (i < N_NODES) {
        int row = g_row[i] + boff;
        g_row[i] = row;
        g_cursor[i] = row;
        g_invd[i] = 1.f / fmaxf((float)g_cnt[i], 1.f);
    }
    if (b == 0 && t == 0) g_row[N_NODES] = N_EDGES;
}

// ---------------- mma helpers ----------------------------------------------------
__device__ __forceinline__ void ldsm_x4(uint32_t* r, uint32_t addr) {
    asm volatile("ldmatrix.sync.aligned.m8n8.x4.shared.b16 {%0,%1,%2,%3}, [%4];"
                 : "=r"(r[0]), "=r"(r[1]), "=r"(r[2]), "=r"(r[3]) : "r"(addr));
}
__device__ __forceinline__ void ldsm_x4t(uint32_t* r, uint32_t addr) {
    asm volatile("ldmatrix.sync.aligned.m8n8.x4.trans.shared.b16 {%0,%1,%2,%3}, [%4];"
                 : "=r"(r[0]), "=r"(r[1]), "=r"(r[2]), "=r"(r[3]) : "r"(addr));
}
__device__ __forceinline__ void mma_f16(float* d, const uint32_t* a, const uint32_t* b) {
    asm volatile(
        "mma.sync.aligned.m16n8k16.row.col.f32.f16.f16.f32 "
        "{%0,%1,%2,%3}, {%4,%5,%6,%7}, {%8,%9}, {%0,%1,%2,%3};"
        : "+f"(d[0]), "+f"(d[1]), "+f"(d[2]), "+f"(d[3])
        : "r"(a[0]), "r"(a[1]), "r"(a[2]), "r"(a[3]), "r"(b[0]), "r"(b[1]));
}
__device__ __forceinline__ void cp16(uint32_t smem_addr, const void* gptr) {
    asm volatile("cp.async.cg.shared.global [%0], [%1], 16;"
                 :: "r"(smem_addr), "l"(gptr) : "memory");
}

#define SROW 136                          // row stride in halfs (128+8)
#define GX_A 0
#define GX_B (128 * SROW * 2)             // 34816
#define GX_SMEM (2 * 128 * SROW * 2)      // 69632
#define GA_WC GX_SMEM
#define GA_BIAS (GA_WC + 128 * 4 * 4)
#define GA_SMEM (GA_BIAS + 128 * 4)       // 72192

// ---------------- gemm_x pair: 2 m-tiles, B loaded once (f16 out) ----------------
__device__ __forceinline__ void gemmx_tile2(int mt0, int nb, char* smem, int tid) {
    const uint32_t sm_base = (uint32_t)__cvta_generic_to_shared(smem);
    const uint32_t as_u = sm_base + GX_A;
    const uint32_t bs_u = sm_base + GX_B;
    const int warp = tid >> 5, lane = tid & 31;
    const int wm = warp >> 2, wn = warp & 3;
    const int g8 = lane >> 2, t = lane & 3;
    const int block_n = nb * 128;

    // ---- B once: 128 k-rows (W1r half) x 128 n-cols ----
    #pragma unroll
    for (int i = 0; i < 8; i++) {
        int id = tid + i * 256;          // 0..2047
        int k = id >> 4;                 // 0..127
        int nc = (id & 15) * 8;          // 0..120
        cp16(bs_u + (k * SROW + nc) * 2,
             g_Wh + (128 + k) * HID_DIM + block_n + nc);
    }
    asm volatile("cp.async.commit_group;" ::: "memory");

    const uint32_t a_lane = ((wm * 64 + (lane & 15)) * SROW + (lane >> 4) * 8) * 2;
    const uint32_t b_lane = ((lane & 15) * SROW + (lane >> 4) * 8) * 2;

    #pragma unroll
    for (int tt = 0; tt < 2; tt++) {
        const int block_m = (mt0 + tt) * 128;
        // A loads: 2 phases of 64 k
        #pragma unroll
        for (int ph = 0; ph < 2; ph++) {
            const int kb = ph * 64;
            #pragma unroll
            for (int i = 0; i < 4; i++) {
                int id = tid + i * 256;      // 0..1023
                int row = id >> 3;           // 0..127
                int ch = (id & 7) * 8;       // 0..56
                cp16(as_u + (row * SROW + kb + ch) * 2,
                     g_xh + (long long)(block_m + row) * IN_DIM + kb + ch);
            }
            asm volatile("cp.async.commit_group;" ::: "memory");
        }

        float acc[4][4][4] = {};
        #pragma unroll
        for (int ph = 0; ph < 2; ph++) {
            if (ph == 0) asm volatile("cp.async.wait_group 1;" ::: "memory");
            else         asm volatile("cp.async.wait_group 0;" ::: "memory");
            __syncthreads();
            #pragma unroll
            for (int ks = 0; ks < 4; ks++) {
                const int kk = ph * 64 + ks * 16;
                uint32_t af[4][4], bf[4][2];
                #pragma unroll
                for (int mi = 0; mi < 4; mi++)
                    ldsm_x4(af[mi], as_u + a_lane + (mi * 16 * SROW + kk) * 2);
                #pragma unroll
                for (int ni2 = 0; ni2 < 2; ni2++) {
                    uint32_t r[4];
                    ldsm_x4t(r, bs_u + b_lane + (kk * SROW + wn * 32 + ni2 * 16) * 2);
                    bf[ni2 * 2 + 0][0] = r[0]; bf[ni2 * 2 + 0][1] = r[1];
                    bf[ni2 * 2 + 1][0] = r[2]; bf[ni2 * 2 + 1][1] = r[3];
                }
                #pragma unroll
                for (int mi = 0; mi < 4; mi++)
                    #pragma unroll
                    for (int ni = 0; ni < 4; ni++)
                        mma_f16(acc[mi][ni], af[mi], bf[ni]);
            }
        }

        #pragma unroll
        for (int mi = 0; mi < 4; mi++) {
            #pragma unroll
            for (int half = 0; half < 2; half++) {
                const int m = block_m + wm * 64 + mi * 16 + g8 + half * 8;
                #pragma unroll
                for (int ni = 0; ni < 4; ni++) {
                    const int n0 = block_n + wn * 32 + ni * 8 + 2 * t;
                    uint32_t v = packh2(acc[mi][ni][half * 2 + 0],
                                        acc[mi][ni][half * 2 + 1]);
                    *reinterpret_cast<uint32_t*>(g_hparth + (long long)m * HID_DIM + n0) = v;
                }
            }
        }
        __syncthreads();   // A buffer reusable by next tile
    }
}

// ---------------- 3. K3: gemm_x half 0 + reorder ---------------------------------
__global__ __launch_bounds__(256, 2)
void k3_kernel(const int* __restrict__ edge_index) {
    extern __shared__ __align__(16) char smem[];
    if (blockIdx.x < GX_CTAS) {
        gemmx_tile2((int)(blockIdx.x >> 2) * 2, (int)(blockIdx.x & 3), smem, threadIdx.x);
        return;
    }
    int id = (blockIdx.x - GX_CTAS) * 256 + threadIdx.x;
    int e0 = id * 2;
    if (e0 >= N_EDGES) return;
    int e1 = e0 + 1;
    int src0 = edge_index[e0];
    int dst0 = edge_index[N_EDGES + e0];
    int src1 = 0, dst1 = 0;
    bool has1 = (e1 < N_EDGES);
    if (has1) { src1 = edge_index[e1]; dst1 = edge_index[N_EDGES + e1]; }
    int p0 = atomicAdd(&g_cursor[dst0], 1);
    int p1 = has1 ? atomicAdd(&g_cursor[dst1], 1) : 0;
    g_csr[p0] = src0;
    if (has1) g_csr[p1] = src1;
}

// ---------------- 4. K4: gemm_x half 1 + gather-mean aggregation -----------------
__global__ __launch_bounds__(256, 2)
void k4_kernel() {
    extern __shared__ __align__(16) char smem[];
    if (blockIdx.x < GX_CTAS) {
        gemmx_tile2(196 + (int)(blockIdx.x >> 2) * 2, (int)(blockIdx.x & 3),
                    smem, threadIdx.x);
        return;
    }
    int id = (blockIdx.x - GX_CTAS) * 256 + threadIdx.x;
    int node = id >> 4;
    int l16 = id & 15;
    if (node >= N_PAD) return;
    float s[8] = {};
    if (node < N_NODES) {
        const int beg = g_row[node];
        const int end = g_row[node + 1];
        int e = beg;
        for (; e + 3 < end; e += 4) {
            int i0 = g_csr[e], i1 = g_csr[e + 1], i2 = g_csr[e + 2], i3 = g_csr[e + 3];
            uint4 v0 = *reinterpret_cast<const uint4*>(g_xh + (long long)i0 * IN_DIM + l16 * 8);
            uint4 v1 = *reinterpret_cast<const uint4*>(g_xh + (long long)i1 * IN_DIM + l16 * 8);
            uint4 v2 = *reinterpret_cast<const uint4*>(g_xh + (long long)i2 * IN_DIM + l16 * 8);
            uint4 v3 = *reinterpret_cast<const uint4*>(g_xh + (long long)i3 * IN_DIM + l16 * 8);
            const __half2* h0 = reinterpret_cast<const __half2*>(&v0);
            const __half2* h1 = reinterpret_cast<const __half2*>(&v1);
            const __half2* h2 = reinterpret_cast<const __half2*>(&v2);
            const __half2* h3 = reinterpret_cast<const __half2*>(&v3);
            #pragma unroll
            for (int j = 0; j < 4; j++) {
                float2 f0 = __half22float2(h0[j]);
                float2 f1 = __half22float2(h1[j]);
                float2 f2 = __half22float2(h2[j]);
                float2 f3 = __half22float2(h3[j]);
                s[j * 2 + 0] += (f0.x + f1.x) + (f2.x + f3.x);
                s[j * 2 + 1] += (f0.y + f1.y) + (f2.y + f3.y);
            }
        }
        for (; e < end; e++) {
            int i0 = g_csr[e];
            uint4 v0 = *reinterpret_cast<const uint4*>(g_xh + (long long)i0 * IN_DIM + l16 * 8);
            const __half2* h0 = reinterpret_cast<const __half2*>(&v0);
            #pragma unroll
            for (int j = 0; j < 4; j++) {
                float2 f0 = __half22float2(h0[j]);
                s[j * 2 + 0] += f0.x;
                s[j * 2 + 1] += f0.y;
            }
        }
        const float invd = g_invd[node];
        #pragma unroll
        for (int j = 0; j < 8; j++) s[j] *= invd;
    }
    uint4 o;
    o.x = packh2(s[0], s[1]); o.y = packh2(s[2], s[3]);
    o.z = packh2(s[4], s[5]); o.w = packh2(s[6], s[7]);
    *reinterpret_cast<uint4*>(g_aggh + (long long)node * IN_DIM + l16 * 8) = o;
}

// ---------------- 5. gemm_agg: 2 m-tiles/CTA, B+Wc once --------------------------
__global__ __launch_bounds__(256, 2)
void gemm_agg_kernel(const float* __restrict__ b1,
                     const float* __restrict__ W2l,
                     const float* __restrict__ W2r) {
    extern __shared__ __align__(16) char smem[];
    float (*Wc)[4] = reinterpret_cast<float(*)[4]>(smem + GA_WC);
    float* bias_s = reinterpret_cast<float*>(smem + GA_BIAS);

    const uint32_t sm_base = (uint32_t)__cvta_generic_to_shared(smem);
    const uint32_t as_u = sm_base + GX_A;
    const uint32_t bs_u = sm_base + GX_B;
    const int tid = threadIdx.x;
    const int warp = tid >> 5, lane = tid & 31;
    const int wm = warp >> 2, wn = warp & 3;
    const int g8 = lane >> 2, t = lane & 3;
    const int mt0 = blockIdx.y * 2;
    const int block_n = blockIdx.x * 128;

    // ---- B once: 128 k-rows (W1l half) x 128 n-cols ----
    #pragma unroll
    for (int i = 0; i < 8; i++) {
        int id = tid + i * 256;
        int k = id >> 4;
        int nc = (id & 15) * 8;
        cp16(bs_u + (k * SROW + nc) * 2, g_Wh + k * HID_DIM + block_n + nc);
    }
    asm volatile("cp.async.commit_group;" ::: "memory");

    // epilogue weights/bias once
    for (int idx = tid; idx < 128 * 4; idx += 256) {
        int nn = idx >> 2, c = idx & 3;
        int n = block_n + nn;
        Wc[nn][c] = (c < 2) ? W2l[n * 2 + c] : W2r[n * 2 + (c - 2)];
    }
    for (int idx = tid; idx < 128; idx += 256) bias_s[idx] = b1[block_n + idx];

    const uint32_t a_lane = ((wm * 64 + (lane & 15)) * SROW + (lane >> 4) * 8) * 2;
    const uint32_t b_lane = ((lane & 15) * SROW + (lane >> 4) * 8) * 2;

    #pragma unroll
    for (int tt = 0; tt < 2; tt++) {
        const int block_m = (mt0 + tt) * 128;
        #pragma unroll
        for (int ph = 0; ph < 2; ph++) {
            const int kb = ph * 64;
            #pragma unroll
            for (int i = 0; i < 4; i++) {
                int id = tid + i * 256;
                int row = id >> 3;
                int ch = (id & 7) * 8;
                cp16(as_u + (row * SROW + kb + ch) * 2,
                     g_aggh + (long long)(block_m + row) * IN_DIM + kb + ch);
            }
            asm volatile("cp.async.commit_group;" ::: "memory");
        }

        float acc[4][4][4] = {};
        #pragma unroll
        for (int ph = 0; ph < 2; ph++) {
            if (ph == 0) asm volatile("cp.async.wait_group 1;" ::: "memory");
            else         asm volatile("cp.async.wait_group 0;" ::: "memory");
            __syncthreads();
            #pragma unroll
            for (int ks = 0; ks < 4; ks++) {
                const int kk = ph * 64 + ks * 16;
                uint32_t af[4][4], bf[4][2];
                #pragma unroll
                for (int mi = 0; mi < 4; mi++)
                    ldsm_x4(af[mi], as_u + a_lane + (mi * 16 * SROW + kk) * 2);
                #pragma unroll
                for (int ni2 = 0; ni2 < 2; ni2++) {
                    uint32_t r[4];
                    ldsm_x4t(r, bs_u + b_lane + (kk * SROW + wn * 32 + ni2 * 16) * 2);
                    bf[ni2 * 2 + 0][0] = r[0]; bf[ni2 * 2 + 0][1] = r[1];
                    bf[ni2 * 2 + 1][0] = r[2]; bf[ni2 * 2 + 1][1] = r[3];
                }
                #pragma unroll
                for (int mi = 0; mi < 4; mi++)
                    #pragma unroll
                    for (int ni = 0; ni < 4; ni++)
                        mma_f16(acc[mi][ni], af[mi], bf[ni]);
            }
        }

        // epilogue: + hparth(f16) + bias, relu, project, reduce, accumulate
        #pragma unroll
        for (int mi = 0; mi < 4; mi++) {
            #pragma unroll
            for (int half = 0; half < 2; half++) {
                const int m = block_m + wm * 64 + mi * 16 + g8 + half * 8;
                float s0 = 0.f, s1 = 0.f, s2 = 0.f, s3 = 0.f;
                #pragma unroll
                for (int ni = 0; ni < 4; ni++) {
                    const int nl = wn * 32 + ni * 8 + 2 * t;
                    __half2 hh = *reinterpret_cast<const __half2*>(
                        g_hparth + (long long)m * HID_DIM + block_n + nl);
                    float2 hp = __half22float2(hh);
                    #pragma unroll
                    for (int r = 0; r < 2; r++) {
                        float hpv = (r == 0) ? hp.x : hp.y;
                        float hv = fmaxf(acc[mi][ni][half * 2 + r] + hpv + bias_s[nl + r], 0.f);
                        s0 += hv * Wc[nl + r][0];
                        s1 += hv * Wc[nl + r][1];
                        s2 += hv * Wc[nl + r][2];
                        s3 += hv * Wc[nl + r][3];
                    }
                }
                #pragma unroll
                for (int off = 1; off <= 2; off <<= 1) {
                    s0 += __shfl_xor_sync(0xffffffff, s0, off);
                    s1 += __shfl_xor_sync(0xffffffff, s1, off);
                    s2 += __shfl_xor_sync(0xffffffff, s2, off);
                    s3 += __shfl_xor_sync(0xffffffff, s3, off);
                }
                if (t == 0 && m < N_NODES) {
                    atomicAdd(&g_pq[m * 4 + 0], s0);
                    atomicAdd(&g_pq[m * 4 + 1], s1);
                    atomicAdd(&g_pq[m * 4 + 2], s2);
                    atomicAdd(&g_pq[m * 4 + 3], s3);
                }
            }
        }
        __syncthreads();   // A buffer reusable by next tile
    }
}

// ---------------- 6. final: gather + log_softmax + reset g_cnt -------------------
__global__ void final_kernel(const float* __restrict__ b2,
                             float* __restrict__ out) {
    int n = blockIdx.x * blockDim.x + threadIdx.x;
    if (n >= N_NODES) return;
    g_cnt[n] = 0;
    const int beg = g_row[n];
    const int end = g_row[n + 1];
    float s0 = 0.f, s1 = 0.f;
    int e = beg;
    for (; e + 1 < end; e += 2) {
        int u = g_csr[e], v = g_csr[e + 1];
        float2 pu = *reinterpret_cast<const float2*>(&g_pq[u * 4]);
        float2 pv = *reinterpret_cast<const float2*>(&g_pq[v * 4]);
        s0 += pu.x + pv.x; s1 += pu.y + pv.y;
    }
    if (e < end) {
        int u = g_csr[e];
        float2 pu = *reinterpret_cast<const float2*>(&g_pq[u * 4]);
        s0 += pu.x; s1 += pu.y;
    }
    const float invd = g_invd[n];
    float o0 = s0 * invd + b2[0] + g_pq[n * 4 + 2];
    float o1 = s1 * invd + b2[1] + g_pq[n * 4 + 3];
    float m = fmaxf(o0, o1);
    float lse = m + logf(expf(o0 - m) + expf(o1 - m));
    out[n * 2 + 0] = o0 - lse;
    out[n * 2 + 1] = o1 - lse;
}

// ---------------- launcher ---------------------------------------------------------
extern "C" void kernel_launch(void* const* d_in, const int* in_sizes, int n_in,
                              void* d_out, int out_size) {
    const float* x    = (const float*)d_in[0];
    const float* W1l  = (const float*)d_in[1];
    const float* b1   = (const float*)d_in[2];
    const float* W1r  = (const float*)d_in[3];
    const float* W2l  = (const float*)d_in[4];
    const float* b2   = (const float*)d_in[5];
    const float* W2r  = (const float*)d_in[6];
    const int*   ei   = (const int*)d_in[7];
    float* out = (float*)d_out;

    cudaFuncSetAttribute(k3_kernel,
                         cudaFuncAttributeMaxDynamicSharedMemorySize, GX_SMEM);
    cudaFuncSetAttribute(k4_kernel,
                         cudaFuncAttributeMaxDynamicSharedMemorySize, GX_SMEM);
    cudaFuncSetAttribute(gemm_agg_kernel,
                         cudaFuncAttributeMaxDynamicSharedMemorySize, GA_SMEM);

    int prep_threads = N_PAD * IN_DIM / 8;
    prep_kernel<<<(prep_threads + 255) / 256, 256>>>(x, W1l, W1r, ei);
    scan1_kernel<<<49, 1024>>>();
    scan2_kernel<<<49, 1024>>>();

    {   // gemm_x half 0 (98 pairs x 4 n-blocks) + reorder
        int reorder_blocks = (N_EDGES / 2 + 255) / 256;          // 1172
        k3_kernel<<<GX_CTAS + reorder_blocks, 256, GX_SMEM>>>(ei);
    }
    {   // gemm_x half 1 + aggregate
        int agg_blocks = (N_PAD * 16) / 256;                      // 3136
        k4_kernel<<<GX_CTAS + agg_blocks, 256, GX_SMEM>>>();
    }
    {
        dim3 grid(HID_DIM / 128, N_MTILES / 2);
        gemm_agg_kernel<<<grid, 256, GA_SMEM>>>(b1, W2l, W2r);
    }
    final_kernel<<<(N_NODES + 255) / 256, 256>>>(b2, out);
}

// round 15
// speedup vs baseline: 1.1975x; 1.0015x over previous
#include <cuda_runtime.h>
#include <cuda_fp16.h>
#include <math.h>
#include <stdint.h>

#define N_NODES 50000
#define N_PAD   50176          // 392 * 128
#define N_HALF  25088          // 196 * 128
#define N_EDGES 600000
#define IN_DIM  128
#define HID_DIM 512
#define N_MTILES 392
#define GX_CTAS 784            // 196 m-tiles * 4 n-blocks per half
#define AGG_HALF_BLOCKS 1568   // 25088 nodes * 16 threads / 256

// ---------------- scratch ----------------------------------------------------
__device__ int   g_cnt[N_NODES];          // zero-init; final_kernel re-zeroes
__device__ int   g_bsum[64];
__device__ int   g_row[N_NODES + 1];
__device__ int   g_cursor[N_NODES];
__device__ int   g_csr[N_EDGES];
__device__ float g_invd[N_NODES];
__device__ __align__(16) __half g_xh  [N_PAD * IN_DIM];
__device__ __align__(16) __half g_aggh[N_PAD * IN_DIM];
__device__ __align__(16) __half g_Wh  [256 * HID_DIM];    // [k][n]: k<128 W1l else W1r
__device__ __align__(16) __half g_hparth[(long long)N_PAD * HID_DIM];  // x @ W1r (f16)
__device__ float g_pq[N_NODES * 4];

__device__ __forceinline__ uint32_t packh2(float a, float b) {
    __half2 h = __floats2half2_rn(a, b);
    return *reinterpret_cast<uint32_t*>(&h);
}

// ---------------- 0. prep: zero pq + convert x/W + histogram -------------------
__global__ void prep_kernel(const float* __restrict__ x,
                            const float* __restrict__ W1l,
                            const float* __restrict__ W1r,
                            const int* __restrict__ edge_index) {
    int i = blockIdx.x * blockDim.x + threadIdx.x;
    if (i < N_NODES * 4) g_pq[i] = 0.f;
    if (i < N_EDGES) atomicAdd(&g_cnt[edge_index[N_EDGES + i]], 1);
    const int xtot = N_PAD * IN_DIM / 8;
    if (i < xtot) {
        long long base = (long long)i * 8;
        int m = (int)(base / IN_DIM);
        uint4 o;
        if (m < N_NODES) {
            float4 v0 = *reinterpret_cast<const float4*>(x + base);
            float4 v1 = *reinterpret_cast<const float4*>(x + base + 4);
            o.x = packh2(v0.x, v0.y); o.y = packh2(v0.z, v0.w);
            o.z = packh2(v1.x, v1.y); o.w = packh2(v1.z, v1.w);
        } else o = make_uint4(0, 0, 0, 0);
        *reinterpret_cast<uint4*>(g_xh + base) = o;
    }
    const int wtot = 256 * HID_DIM / 4;
    if (i < wtot) {
        int base = i * 4;
        int k = base >> 9;
        int n = base & 511;
        const float* W = (k < IN_DIM) ? (W1l + k * HID_DIM + n)
                                      : (W1r + (k - IN_DIM) * HID_DIM + n);
        float4 v = *reinterpret_cast<const float4*>(W);
        uint2 o; o.x = packh2(v.x, v.y); o.y = packh2(v.z, v.w);
        *reinterpret_cast<uint2*>(g_Wh + base) = o;
    }
}

// ---------------- 1. scan phase 1 ------------------------------------------------
__global__ void scan1_kernel() {
    __shared__ int sm[1024];
    const int b = blockIdx.x, t = threadIdx.x;
    const int i = b * 1024 + t;
    int c = (i < N_NODES) ? g_cnt[i] : 0;
    sm[t] = c;
    __syncthreads();
    for (int off = 1; off < 1024; off <<= 1) {
        int u = (t >= off) ? sm[t - off] : 0;
        __syncthreads();
        sm[t] += u;
        __syncthreads();
    }
    int incl = sm[t];
    if (i < N_NODES) g_row[i] = incl - c;
    if (t == 1023) g_bsum[b] = incl;
}

// ---------------- 2. scan phase 2 ------------------------------------------------
__global__ void scan2_kernel() {
    __shared__ int bs[64];
    const int b = blockIdx.x, t = threadIdx.x;
    if (t < 49) bs[t] = g_bsum[t];
    __syncthreads();
    int boff = 0;
    for (int j = 0; j < b; j++) boff += bs[j];
    const int i = b * 1024 + t;
    if (i < N_NODES) {
        int row = g_row[i] + boff;
        g_row[i] = row;
        g_cursor[i] = row;
        g_invd[i] = 1.f / fmaxf((float)g_cnt[i], 1.f);
    }
    if (b == 0 && t == 0) g_row[N_NODES] = N_EDGES;
}

// ---------------- mma helpers ----------------------------------------------------
__device__ __forceinline__ void ldsm_x4(uint32_t* r, uint32_t addr) {
    asm volatile("ldmatrix.sync.aligned.m8n8.x4.shared.b16 {%0,%1,%2,%3}, [%4];"
                 : "=r"(r[0]), "=r"(r[1]), "=r"(r[2]), "=r"(r[3]) : "r"(addr));
}
__device__ __forceinline__ void ldsm_x4t(uint32_t* r, uint32_t addr) {
    asm volatile("ldmatrix.sync.aligned.m8n8.x4.trans.shared.b16 {%0,%1,%2,%3}, [%4];"
                 : "=r"(r[0]), "=r"(r[1]), "=r"(r[2]), "=r"(r[3]) : "r"(addr));
}
__device__ __forceinline__ void mma_f16(float* d, const uint32_t* a, const uint32_t* b) {
    asm volatile(
        "mma.sync.aligned.m16n8k16.row.col.f32.f16.f16.f32 "
        "{%0,%1,%2,%3}, {%4,%5,%6,%7}, {%8,%9}, {%0,%1,%2,%3};"
        : "+f"(d[0]), "+f"(d[1]), "+f"(d[2]), "+f"(d[3])
        : "r"(a[0]), "r"(a[1]), "r"(a[2]), "r"(a[3]), "r"(b[0]), "r"(b[1]));
}
__device__ __forceinline__ void cp16(uint32_t smem_addr, const void* gptr) {
    asm volatile("cp.async.cg.shared.global [%0], [%1], 16;"
                 :: "r"(smem_addr), "l"(gptr) : "memory");
}

#define SROW 136                          // row stride in halfs (128+8)
#define GX_A 0
#define GX_B (128 * SROW * 2)             // 34816
#define GX_SMEM (2 * 128 * SROW * 2)      // 69632
#define GA_WC GX_SMEM
#define GA_BIAS (GA_WC + 128 * 4 * 4)
#define GA_SMEM (GA_BIAS + 128 * 4)       // 72192

// ---------------- gemm_x tile: hparth[mt, nb] = x_tile @ W1r_tile (f16 out) ------
__device__ __forceinline__ void gemmx_tile(int mt, int nb, char* smem, int tid) {
    const uint32_t sm_base = (uint32_t)__cvta_generic_to_shared(smem);
    const uint32_t as_u = sm_base + GX_A;
    const uint32_t bs_u = sm_base + GX_B;
    const int warp = tid >> 5, lane = tid & 31;
    const int wm = warp >> 2, wn = warp & 3;
    const int g8 = lane >> 2, t = lane & 3;
    const int block_m = mt * 128, block_n = nb * 128;

    #pragma unroll
    for (int ph = 0; ph < 2; ph++) {
        const int kb = ph * 64;
        #pragma unroll
        for (int i = 0; i < 4; i++) {
            int id = tid + i * 256;      // 0..1023
            int row = id >> 3;           // 0..127
            int ch = (id & 7) * 8;       // 0..56
            cp16(as_u + (row * SROW + kb + ch) * 2,
                 g_xh + (long long)(block_m + row) * IN_DIM + kb + ch);
        }
        #pragma unroll
        for (int i = 0; i < 4; i++) {
            int id = tid + i * 256;      // 0..1023
            int k = id >> 4;             // 0..63
            int nc = (id & 15) * 8;      // 0..120
            cp16(bs_u + ((kb + k) * SROW + nc) * 2,
                 g_Wh + (128 + kb + k) * HID_DIM + block_n + nc);
        }
        asm volatile("cp.async.commit_group;" ::: "memory");
    }

    const uint32_t a_lane = ((wm * 64 + (lane & 15)) * SROW + (lane >> 4) * 8) * 2;
    const uint32_t b_lane = ((lane & 15) * SROW + (lane >> 4) * 8) * 2;

    float acc[4][4][4] = {};
    #pragma unroll
    for (int ph = 0; ph < 2; ph++) {
        if (ph == 0) asm volatile("cp.async.wait_group 1;" ::: "memory");
        else         asm volatile("cp.async.wait_group 0;" ::: "memory");
        __syncthreads();
        #pragma unroll
        for (int ks = 0; ks < 4; ks++) {
            const int kk = ph * 64 + ks * 16;
            uint32_t af[4][4], bf[4][2];
            #pragma unroll
            for (int mi = 0; mi < 4; mi++)
                ldsm_x4(af[mi], as_u + a_lane + (mi * 16 * SROW + kk) * 2);
            #pragma unroll
            for (int ni2 = 0; ni2 < 2; ni2++) {
                uint32_t r[4];
                ldsm_x4t(r, bs_u + b_lane + (kk * SROW + wn * 32 + ni2 * 16) * 2);
                bf[ni2 * 2 + 0][0] = r[0]; bf[ni2 * 2 + 0][1] = r[1];
                bf[ni2 * 2 + 1][0] = r[2]; bf[ni2 * 2 + 1][1] = r[3];
            }
            #pragma unroll
            for (int mi = 0; mi < 4; mi++)
                #pragma unroll
                for (int ni = 0; ni < 4; ni++)
                    mma_f16(acc[mi][ni], af[mi], bf[ni]);
        }
    }

    #pragma unroll
    for (int mi = 0; mi < 4; mi++) {
        #pragma unroll
        for (int half = 0; half < 2; half++) {
            const int m = block_m + wm * 64 + mi * 16 + g8 + half * 8;
            #pragma unroll
            for (int ni = 0; ni < 4; ni++) {
                const int n0 = block_n + wn * 32 + ni * 8 + 2 * t;
                uint32_t v = packh2(acc[mi][ni][half * 2 + 0],
                                    acc[mi][ni][half * 2 + 1]);
                *reinterpret_cast<uint32_t*>(g_hparth + (long long)m * HID_DIM + n0) = v;
            }
        }
    }
}

// ---------------- gemm_agg tile: agg@W1l + hparth, relu, project, accumulate -----
__device__ __forceinline__ void gemmagg_tile(int mt, int nb, char* smem, int tid,
                                             const float* __restrict__ b1,
                                             const float* __restrict__ W2l,
                                             const float* __restrict__ W2r) {
    float (*Wc)[4] = reinterpret_cast<float(*)[4]>(smem + GA_WC);
    float* bias_s = reinterpret_cast<float*>(smem + GA_BIAS);
    const uint32_t sm_base = (uint32_t)__cvta_generic_to_shared(smem);
    const uint32_t as_u = sm_base + GX_A;
    const uint32_t bs_u = sm_base + GX_B;
    const int warp = tid >> 5, lane = tid & 31;
    const int wm = warp >> 2, wn = warp & 3;
    const int g8 = lane >> 2, t = lane & 3;
    const int block_m = mt * 128;
    const int block_n = nb * 128;

    #pragma unroll
    for (int ph = 0; ph < 2; ph++) {
        const int kb = ph * 64;
        #pragma unroll
        for (int i = 0; i < 4; i++) {
            int id = tid + i * 256;
            int row = id >> 3;
            int ch = (id & 7) * 8;
            cp16(as_u + (row * SROW + kb + ch) * 2,
                 g_aggh + (long long)(block_m + row) * IN_DIM + kb + ch);
        }
        #pragma unroll
        for (int i = 0; i < 4; i++) {
            int id = tid + i * 256;
            int k = id >> 4;
            int nc = (id & 15) * 8;
            cp16(bs_u + ((kb + k) * SROW + nc) * 2,
                 g_Wh + (kb + k) * HID_DIM + block_n + nc);
        }
        asm volatile("cp.async.commit_group;" ::: "memory");
    }

    for (int idx = tid; idx < 128 * 4; idx += 256) {
        int nn = idx >> 2, c = idx & 3;
        int n = block_n + nn;
        Wc[nn][c] = (c < 2) ? W2l[n * 2 + c] : W2r[n * 2 + (c - 2)];
    }
    for (int idx = tid; idx < 128; idx += 256) bias_s[idx] = b1[block_n + idx];

    const uint32_t a_lane = ((wm * 64 + (lane & 15)) * SROW + (lane >> 4) * 8) * 2;
    const uint32_t b_lane = ((lane & 15) * SROW + (lane >> 4) * 8) * 2;

    float acc[4][4][4] = {};
    #pragma unroll
    for (int ph = 0; ph < 2; ph++) {
        if (ph == 0) asm volatile("cp.async.wait_group 1;" ::: "memory");
        else         asm volatile("cp.async.wait_group 0;" ::: "memory");
        __syncthreads();
        #pragma unroll
        for (int ks = 0; ks < 4; ks++) {
            const int kk = ph * 64 + ks * 16;
            uint32_t af[4][4], bf[4][2];
            #pragma unroll
            for (int mi = 0; mi < 4; mi++)
                ldsm_x4(af[mi], as_u + a_lane + (mi * 16 * SROW + kk) * 2);
            #pragma unroll
            for (int ni2 = 0; ni2 < 2; ni2++) {
                uint32_t r[4];
                ldsm_x4t(r, bs_u + b_lane + (kk * SROW + wn * 32 + ni2 * 16) * 2);
                bf[ni2 * 2 + 0][0] = r[0]; bf[ni2 * 2 + 0][1] = r[1];
                bf[ni2 * 2 + 1][0] = r[2]; bf[ni2 * 2 + 1][1] = r[3];
            }
            #pragma unroll
            for (int mi = 0; mi < 4; mi++)
                #pragma unroll
                for (int ni = 0; ni < 4; ni++)
                    mma_f16(acc[mi][ni], af[mi], bf[ni]);
        }
    }

    #pragma unroll
    for (int mi = 0; mi < 4; mi++) {
        #pragma unroll
        for (int half = 0; half < 2; half++) {
            const int m = block_m + wm * 64 + mi * 16 + g8 + half * 8;
            float s0 = 0.f, s1 = 0.f, s2 = 0.f, s3 = 0.f;
            #pragma unroll
            for (int ni = 0; ni < 4; ni++) {
                const int nl = wn * 32 + ni * 8 + 2 * t;
                __half2 hh = *reinterpret_cast<const __half2*>(
                    g_hparth + (long long)m * HID_DIM + block_n + nl);
                float2 hp = __half22float2(hh);
                #pragma unroll
                for (int r = 0; r < 2; r++) {
                    float hpv = (r == 0) ? hp.x : hp.y;
                    float hv = fmaxf(acc[mi][ni][half * 2 + r] + hpv + bias_s[nl + r], 0.f);
                    s0 += hv * Wc[nl + r][0];
                    s1 += hv * Wc[nl + r][1];
                    s2 += hv * Wc[nl + r][2];
                    s3 += hv * Wc[nl + r][3];
                }
            }
            #pragma unroll
            for (int off = 1; off <= 2; off <<= 1) {
                s0 += __shfl_xor_sync(0xffffffff, s0, off);
                s1 += __shfl_xor_sync(0xffffffff, s1, off);
                s2 += __shfl_xor_sync(0xffffffff, s2, off);
                s3 += __shfl_xor_sync(0xffffffff, s3, off);
            }
            if (t == 0 && m < N_NODES) {
                atomicAdd(&g_pq[m * 4 + 0], s0);
                atomicAdd(&g_pq[m * 4 + 1], s1);
                atomicAdd(&g_pq[m * 4 + 2], s2);
                atomicAdd(&g_pq[m * 4 + 3], s3);
            }
        }
    }
}

// ---------------- aggregate body (node range) -------------------------------------
__device__ __forceinline__ void aggregate_body(int id, int node_base) {
    int node = node_base + (id >> 4);
    int l16 = id & 15;
    if (node >= N_PAD) return;
    float s[8] = {};
    if (node < N_NODES) {
        const int beg = g_row[node];
        const int end = g_row[node + 1];
        int e = beg;
        for (; e + 3 < end; e += 4) {
            int i0 = g_csr[e], i1 = g_csr[e + 1], i2 = g_csr[e + 2], i3 = g_csr[e + 3];
            uint4 v0 = *reinterpret_cast<const uint4*>(g_xh + (long long)i0 * IN_DIM + l16 * 8);
            uint4 v1 = *reinterpret_cast<const uint4*>(g_xh + (long long)i1 * IN_DIM + l16 * 8);
            uint4 v2 = *reinterpret_cast<const uint4*>(g_xh + (long long)i2 * IN_DIM + l16 * 8);
            uint4 v3 = *reinterpret_cast<const uint4*>(g_xh + (long long)i3 * IN_DIM + l16 * 8);
            const __half2* h0 = reinterpret_cast<const __half2*>(&v0);
            const __half2* h1 = reinterpret_cast<const __half2*>(&v1);
            const __half2* h2 = reinterpret_cast<const __half2*>(&v2);
            const __half2* h3 = reinterpret_cast<const __half2*>(&v3);
            #pragma unroll
            for (int j = 0; j < 4; j++) {
                float2 f0 = __half22float2(h0[j]);
                float2 f1 = __half22float2(h1[j]);
                float2 f2 = __half22float2(h2[j]);
                float2 f3 = __half22float2(h3[j]);
                s[j * 2 + 0] += (f0.x + f1.x) + (f2.x + f3.x);
                s[j * 2 + 1] += (f0.y + f1.y) + (f2.y + f3.y);
            }
        }
        for (; e < end; e++) {
            int i0 = g_csr[e];
            uint4 v0 = *reinterpret_cast<const uint4*>(g_xh + (long long)i0 * IN_DIM + l16 * 8);
            const __half2* h0 = reinterpret_cast<const __half2*>(&v0);
            #pragma unroll
            for (int j = 0; j < 4; j++) {
                float2 f0 = __half22float2(h0[j]);
                s[j * 2 + 0] += f0.x;
                s[j * 2 + 1] += f0.y;
            }
        }
        const float invd = g_invd[node];
        #pragma unroll
        for (int j = 0; j < 8; j++) s[j] *= invd;
    }
    uint4 o;
    o.x = packh2(s[0], s[1]); o.y = packh2(s[2], s[3]);
    o.z = packh2(s[4], s[5]); o.w = packh2(s[6], s[7]);
    *reinterpret_cast<uint4*>(g_aggh + (long long)node * IN_DIM + l16 * 8) = o;
}

// ---------------- 3. K3: gemm_x half 0 + reorder ---------------------------------
__global__ __launch_bounds__(256, 2)
void k3_kernel(const int* __restrict__ edge_index) {
    extern __shared__ __align__(16) char smem[];
    if (blockIdx.x < GX_CTAS) {
        gemmx_tile((int)(blockIdx.x >> 2), (int)(blockIdx.x & 3), smem, threadIdx.x);
        return;
    }
    int id = (blockIdx.x - GX_CTAS) * 256 + threadIdx.x;
    int e0 = id * 2;
    if (e0 >= N_EDGES) return;
    int e1 = e0 + 1;
    int src0 = edge_index[e0];
    int dst0 = edge_index[N_EDGES + e0];
    int src1 = 0, dst1 = 0;
    bool has1 = (e1 < N_EDGES);
    if (has1) { src1 = edge_index[e1]; dst1 = edge_index[N_EDGES + e1]; }
    int p0 = atomicAdd(&g_cursor[dst0], 1);
    int p1 = has1 ? atomicAdd(&g_cursor[dst1], 1) : 0;
    g_csr[p0] = src0;
    if (has1) g_csr[p1] = src1;
}

// ---------------- 4. K4: gemm_x half 1 + aggregate half 0 ------------------------
__global__ __launch_bounds__(256, 2)
void k4_kernel() {
    extern __shared__ __align__(16) char smem[];
    if (blockIdx.x < GX_CTAS) {
        gemmx_tile(196 + (int)(blockIdx.x >> 2), (int)(blockIdx.x & 3), smem, threadIdx.x);
        return;
    }
    aggregate_body((blockIdx.x - GX_CTAS) * 256 + threadIdx.x, 0);
}

// ---------------- 5. K5: gemm_agg half 0 + aggregate half 1 ----------------------
__global__ __launch_bounds__(256, 2)
void k5_kernel(const float* __restrict__ b1,
               const float* __restrict__ W2l,
               const float* __restrict__ W2r) {
    extern __shared__ __align__(16) char smem[];
    if (blockIdx.x < GX_CTAS) {
        gemmagg_tile((int)(blockIdx.x >> 2), (int)(blockIdx.x & 3), smem, threadIdx.x,
                     b1, W2l, W2r);
        return;
    }
    aggregate_body((blockIdx.x - GX_CTAS) * 256 + threadIdx.x, N_HALF);
}

// ---------------- 6. K6: gemm_agg half 1 ------------------------------------------
__global__ __launch_bounds__(256, 2)
void k6_kernel(const float* __restrict__ b1,
               const float* __restrict__ W2l,
               const float* __restrict__ W2r) {
    extern __shared__ __align__(16) char smem[];
    gemmagg_tile(196 + (int)(blockIdx.x >> 2), (int)(blockIdx.x & 3), smem, threadIdx.x,
                 b1, W2l, W2r);
}

// ---------------- 7. final: gather + log_softmax + reset g_cnt -------------------
__global__ void final_kernel(const float* __restrict__ b2,
                             float* __restrict__ out) {
    int n = blockIdx.x * blockDim.x + threadIdx.x;
    if (n >= N_NODES) return;
    g_cnt[n] = 0;
    const int beg = g_row[n];
    const int end = g_row[n + 1];
    float s0 = 0.f, s1 = 0.f;
    int e = beg;
    for (; e + 1 < end; e += 2) {
        int u = g_csr[e], v = g_csr[e + 1];
        float2 pu = *reinterpret_cast<const float2*>(&g_pq[u * 4]);
        float2 pv = *reinterpret_cast<const float2*>(&g_pq[v * 4]);
        s0 += pu.x + pv.x; s1 += pu.y + pv.y;
    }
    if (e < end) {
        int u = g_csr[e];
        float2 pu = *reinterpret_cast<const float2*>(&g_pq[u * 4]);
        s0 += pu.x; s1 += pu.y;
    }
    const float invd = g_invd[n];
    float o0 = s0 * invd + b2[0] + g_pq[n * 4 + 2];
    float o1 = s1 * invd + b2[1] + g_pq[n * 4 + 3];
    float m = fmaxf(o0, o1);
    float lse = m + logf(expf(o0 - m) + expf(o1 - m));
    out[n * 2 + 0] = o0 - lse;
    out[n * 2 + 1] = o1 - lse;
}

// ---------------- launcher ---------------------------------------------------------
extern "C" void kernel_launch(void* const* d_in, const int* in_sizes, int n_in,
                              void* d_out, int out_size) {
    const float* x    = (const float*)d_in[0];
    const float* W1l  = (const float*)d_in[1];
    const float* b1   = (const float*)d_in[2];
    const float* W1r  = (const float*)d_in[3];
    const float* W2l  = (const float*)d_in[4];
    const float* b2   = (const float*)d_in[5];
    const float* W2r  = (const float*)d_in[6];
    const int*   ei   = (const int*)d_in[7];
    float* out = (float*)d_out;

    cudaFuncSetAttribute(k3_kernel,
                         cudaFuncAttributeMaxDynamicSharedMemorySize, GX_SMEM);
    cudaFuncSetAttribute(k4_kernel,
                         cudaFuncAttributeMaxDynamicSharedMemorySize, GX_SMEM);
    cudaFuncSetAttribute(k5_kernel,
                         cudaFuncAttributeMaxDynamicSharedMemorySize, GA_SMEM);
    cudaFuncSetAttribute(k6_kernel,
                         cudaFuncAttributeMaxDynamicSharedMemorySize, GA_SMEM);

    int prep_threads = N_PAD * IN_DIM / 8;
    prep_kernel<<<(prep_threads + 255) / 256, 256>>>(x, W1l, W1r, ei);
    scan1_kernel<<<49, 1024>>>();
    scan2_kernel<<<49, 1024>>>();

    {   // gemm_x half 0 + reorder
        int reorder_blocks = (N_EDGES / 2 + 255) / 256;          // 1172
        k3_kernel<<<GX_CTAS + reorder_blocks, 256, GX_SMEM>>>(ei);
    }
    // gemm_x half 1 + aggregate half 0
    k4_kernel<<<GX_CTAS + AGG_HALF_BLOCKS, 256, GX_SMEM>>>();
    // gemm_agg half 0 + aggregate half 1
    k5_kernel<<<GX_CTAS + AGG_HALF_BLOCKS, 256, GA_SMEM>>>(b1, W2l, W2r);
    // gemm_agg half 1
    k6_kernel<<<GX_CTAS, 256, GA_SMEM>>>(b1, W2l, W2r);

    final_kernel<<<(N_NODES + 255) / 256, 256>>>(b2, out);
}

// round 16
// speedup vs baseline: 1.3179x; 1.1005x over previous
#include <cuda_runtime.h>
#include <cuda_fp16.h>
#include <math.h>
#include <stdint.h>

#define N_NODES 50000
#define N_PAD   50176          // 392 * 128
#define N_EDGES 600000
#define IN_DIM  128
#define HID_DIM 512
#define N_MTILES 392

// ---------------- scratch ----------------------------------------------------
__device__ int   g_cnt[N_NODES];          // zero-init; final_kernel re-zeroes
__device__ int   g_bsum[64];
__device__ int   g_row[N_NODES + 1];
__device__ int   g_cursor[N_NODES];
__device__ int   g_csr[N_EDGES];
__device__ float g_invd[N_NODES];
__device__ __align__(16) __half g_xh  [N_PAD * IN_DIM];
__device__ __align__(16) __half g_aggh[N_PAD * IN_DIM];
__device__ __align__(16) __half g_Wh  [256 * HID_DIM];    // [k][n]: k<128 W1l else W1r
__device__ __align__(16) __half g_hparth[(long long)N_PAD * HID_DIM];  // x @ W1r (f16)
__device__ float g_pq[N_NODES * 4];

__device__ __forceinline__ uint32_t packh2(float a, float b) {
    __half2 h = __floats2half2_rn(a, b);
    return *reinterpret_cast<uint32_t*>(&h);
}

// ---------------- 0. prep: zero pq + convert x/W + histogram -------------------
__global__ void prep_kernel(const float* __restrict__ x,
                            const float* __restrict__ W1l,
                            const float* __restrict__ W1r,
                            const int* __restrict__ edge_index) {
    int i = blockIdx.x * blockDim.x + threadIdx.x;
    if (i < N_NODES * 4) g_pq[i] = 0.f;
    if (i < N_EDGES) atomicAdd(&g_cnt[edge_index[N_EDGES + i]], 1);
    const int xtot = N_PAD * IN_DIM / 8;
    if (i < xtot) {
        long long base = (long long)i * 8;
        int m = (int)(base / IN_DIM);
        uint4 o;
        if (m < N_NODES) {
            float4 v0 = *reinterpret_cast<const float4*>(x + base);
            float4 v1 = *reinterpret_cast<const float4*>(x + base + 4);
            o.x = packh2(v0.x, v0.y); o.y = packh2(v0.z, v0.w);
            o.z = packh2(v1.x, v1.y); o.w = packh2(v1.z, v1.w);
        } else o = make_uint4(0, 0, 0, 0);
        *reinterpret_cast<uint4*>(g_xh + base) = o;
    }
    const int wtot = 256 * HID_DIM / 4;
    if (i < wtot) {
        int base = i * 4;
        int k = base >> 9;
        int n = base & 511;
        const float* W = (k < IN_DIM) ? (W1l + k * HID_DIM + n)
                                      : (W1r + (k - IN_DIM) * HID_DIM + n);
        float4 v = *reinterpret_cast<const float4*>(W);
        uint2 o; o.x = packh2(v.x, v.y); o.y = packh2(v.z, v.w);
        *reinterpret_cast<uint2*>(g_Wh + base) = o;
    }
}

// ---------------- 1. scan phase 1 ------------------------------------------------
__global__ void scan1_kernel() {
    __shared__ int sm[1024];
    const int b = blockIdx.x, t = threadIdx.x;
    const int i = b * 1024 + t;
    int c = (i < N_NODES) ? g_cnt[i] : 0;
    sm[t] = c;
    __syncthreads();
    for (int off = 1; off < 1024; off <<= 1) {
        int u = (t >= off) ? sm[t - off] : 0;
        __syncthreads();
        sm[t] += u;
        __syncthreads();
    }
    int incl = sm[t];
    if (i < N_NODES) g_row[i] = incl - c;
    if (t == 1023) g_bsum[b] = incl;
}

// ---------------- 2. scan phase 2 ------------------------------------------------
__global__ void scan2_kernel() {
    __shared__ int bs[64];
    const int b = blockIdx.x, t = threadIdx.x;
    if (t < 49) bs[t] = g_bsum[t];
    __syncthreads();
    int boff = 0;
    for (int j = 0; j < b; j++) boff += bs[j];
    const int i = b * 1024 + t;
    if (i < N_NODES) {
        int row = g_row[i] + boff;
        g_row[i] = row;
        g_cursor[i] = row;
        g_invd[i] = 1.f / fmaxf((float)g_cnt[i], 1.f);
    }
    if (b == 0 && t == 0) g_row[N_NODES] = N_EDGES;
}

// ---------------- 3. reorder (standalone, full occupancy) ------------------------
__global__ void reorder_kernel(const int* __restrict__ edge_index) {
    int i = blockIdx.x * blockDim.x + threadIdx.x;
    int e0 = i * 2;
    if (e0 >= N_EDGES) return;
    int e1 = e0 + 1;
    int src0 = edge_index[e0];
    int dst0 = edge_index[N_EDGES + e0];
    int src1 = 0, dst1 = 0;
    bool has1 = (e1 < N_EDGES);
    if (has1) { src1 = edge_index[e1]; dst1 = edge_index[N_EDGES + e1]; }
    int p0 = atomicAdd(&g_cursor[dst0], 1);
    int p1 = has1 ? atomicAdd(&g_cursor[dst1], 1) : 0;
    g_csr[p0] = src0;
    if (has1) g_csr[p1] = src1;
}

// ---------------- 4. aggregate (standalone, full occupancy) ----------------------
__global__ void aggregate1_kernel() {
    int id = blockIdx.x * blockDim.x + threadIdx.x;
    int node = id >> 4;
    int l16 = id & 15;
    if (node >= N_PAD) return;
    float s[8] = {};
    if (node < N_NODES) {
        const int beg = g_row[node];
        const int end = g_row[node + 1];
        int e = beg;
        for (; e + 3 < end; e += 4) {
            int i0 = g_csr[e], i1 = g_csr[e + 1], i2 = g_csr[e + 2], i3 = g_csr[e + 3];
            uint4 v0 = *reinterpret_cast<const uint4*>(g_xh + (long long)i0 * IN_DIM + l16 * 8);
            uint4 v1 = *reinterpret_cast<const uint4*>(g_xh + (long long)i1 * IN_DIM + l16 * 8);
            uint4 v2 = *reinterpret_cast<const uint4*>(g_xh + (long long)i2 * IN_DIM + l16 * 8);
            uint4 v3 = *reinterpret_cast<const uint4*>(g_xh + (long long)i3 * IN_DIM + l16 * 8);
            const __half2* h0 = reinterpret_cast<const __half2*>(&v0);
            const __half2* h1 = reinterpret_cast<const __half2*>(&v1);
            const __half2* h2 = reinterpret_cast<const __half2*>(&v2);
            const __half2* h3 = reinterpret_cast<const __half2*>(&v3);
            #pragma unroll
            for (int j = 0; j < 4; j++) {
                float2 f0 = __half22float2(h0[j]);
                float2 f1 = __half22float2(h1[j]);
                float2 f2 = __half22float2(h2[j]);
                float2 f3 = __half22float2(h3[j]);
                s[j * 2 + 0] += (f0.x + f1.x) + (f2.x + f3.x);
                s[j * 2 + 1] += (f0.y + f1.y) + (f2.y + f3.y);
            }
        }
        for (; e < end; e++) {
            int i0 = g_csr[e];
            uint4 v0 = *reinterpret_cast<const uint4*>(g_xh + (long long)i0 * IN_DIM + l16 * 8);
            const __half2* h0 = reinterpret_cast<const __half2*>(&v0);
            #pragma unroll
            for (int j = 0; j < 4; j++) {
                float2 f0 = __half22float2(h0[j]);
                s[j * 2 + 0] += f0.x;
                s[j * 2 + 1] += f0.y;
            }
        }
        const float invd = g_invd[node];
        #pragma unroll
        for (int j = 0; j < 8; j++) s[j] *= invd;
    }
    uint4 o;
    o.x = packh2(s[0], s[1]); o.y = packh2(s[2], s[3]);
    o.z = packh2(s[4], s[5]); o.w = packh2(s[6], s[7]);
    *reinterpret_cast<uint4*>(g_aggh + (long long)node * IN_DIM + l16 * 8) = o;
}

// ---------------- mma helpers ----------------------------------------------------
__device__ __forceinline__ void ldsm_x4(uint32_t* r, uint32_t addr) {
    asm volatile("ldmatrix.sync.aligned.m8n8.x4.shared.b16 {%0,%1,%2,%3}, [%4];"
                 : "=r"(r[0]), "=r"(r[1]), "=r"(r[2]), "=r"(r[3]) : "r"(addr));
}
__device__ __forceinline__ void ldsm_x4t(uint32_t* r, uint32_t addr) {
    asm volatile("ldmatrix.sync.aligned.m8n8.x4.trans.shared.b16 {%0,%1,%2,%3}, [%4];"
                 : "=r"(r[0]), "=r"(r[1]), "=r"(r[2]), "=r"(r[3]) : "r"(addr));
}
__device__ __forceinline__ void mma_f16(float* d, const uint32_t* a, const uint32_t* b) {
    asm volatile(
        "mma.sync.aligned.m16n8k16.row.col.f32.f16.f16.f32 "
        "{%0,%1,%2,%3}, {%4,%5,%6,%7}, {%8,%9}, {%0,%1,%2,%3};"
        : "+f"(d[0]), "+f"(d[1]), "+f"(d[2]), "+f"(d[3])
        : "r"(a[0]), "r"(a[1]), "r"(a[2]), "r"(a[3]), "r"(b[0]), "r"(b[1]));
}
__device__ __forceinline__ void cp16(uint32_t smem_addr, const void* gptr) {
    asm volatile("cp.async.cg.shared.global [%0], [%1], 16;"
                 :: "r"(smem_addr), "l"(gptr) : "memory");
}

#define SROW 136                          // row stride in halfs (128+8)
#define GX_A 0
#define GX_B (128 * SROW * 2)             // 34816
#define GX_SMEM (2 * 128 * SROW * 2)      // 69632
#define GA_WC GX_SMEM
#define GA_BIAS (GA_WC + 128 * 4 * 4)
#define GA_SMEM (GA_BIAS + 128 * 4)       // 72192

// ---------------- 5. gemm_x: hparth = x @ W1r (pure, side stream) ----------------
__global__ __launch_bounds__(256, 2)
void gemmx_kernel() {
    extern __shared__ __align__(16) char smem[];
    const uint32_t sm_base = (uint32_t)__cvta_generic_to_shared(smem);
    const uint32_t as_u = sm_base + GX_A;
    const uint32_t bs_u = sm_base + GX_B;
    const int tid = threadIdx.x;
    const int warp = tid >> 5, lane = tid & 31;
    const int wm = warp >> 2, wn = warp & 3;
    const int g8 = lane >> 2, t = lane & 3;
    const int mt = (int)(blockIdx.x >> 2);
    const int nb = (int)(blockIdx.x & 3);
    const int block_m = mt * 128, block_n = nb * 128;

    #pragma unroll
    for (int ph = 0; ph < 2; ph++) {
        const int kb = ph * 64;
        #pragma unroll
        for (int i = 0; i < 4; i++) {
            int id = tid + i * 256;      // 0..1023
            int row = id >> 3;           // 0..127
            int ch = (id & 7) * 8;       // 0..56
            cp16(as_u + (row * SROW + kb + ch) * 2,
                 g_xh + (long long)(block_m + row) * IN_DIM + kb + ch);
        }
        #pragma unroll
        for (int i = 0; i < 4; i++) {
            int id = tid + i * 256;      // 0..1023
            int k = id >> 4;             // 0..63
            int nc = (id & 15) * 8;      // 0..120
            cp16(bs_u + ((kb + k) * SROW + nc) * 2,
                 g_Wh + (128 + kb + k) * HID_DIM + block_n + nc);
        }
        asm volatile("cp.async.commit_group;" ::: "memory");
    }

    const uint32_t a_lane = ((wm * 64 + (lane & 15)) * SROW + (lane >> 4) * 8) * 2;
    const uint32_t b_lane = ((lane & 15) * SROW + (lane >> 4) * 8) * 2;

    float acc[4][4][4] = {};
    #pragma unroll
    for (int ph = 0; ph < 2; ph++) {
        if (ph == 0) asm volatile("cp.async.wait_group 1;" ::: "memory");
        else         asm volatile("cp.async.wait_group 0;" ::: "memory");
        __syncthreads();
        #pragma unroll
        for (int ks = 0; ks < 4; ks++) {
            const int kk = ph * 64 + ks * 16;
            uint32_t af[4][4], bf[4][2];
            #pragma unroll
            for (int mi = 0; mi < 4; mi++)
                ldsm_x4(af[mi], as_u + a_lane + (mi * 16 * SROW + kk) * 2);
            #pragma unroll
            for (int ni2 = 0; ni2 < 2; ni2++) {
                uint32_t r[4];
                ldsm_x4t(r, bs_u + b_lane + (kk * SROW + wn * 32 + ni2 * 16) * 2);
                bf[ni2 * 2 + 0][0] = r[0]; bf[ni2 * 2 + 0][1] = r[1];
                bf[ni2 * 2 + 1][0] = r[2]; bf[ni2 * 2 + 1][1] = r[3];
            }
            #pragma unroll
            for (int mi = 0; mi < 4; mi++)
                #pragma unroll
                for (int ni = 0; ni < 4; ni++)
                    mma_f16(acc[mi][ni], af[mi], bf[ni]);
        }
    }

    #pragma unroll
    for (int mi = 0; mi < 4; mi++) {
        #pragma unroll
        for (int half = 0; half < 2; half++) {
            const int m = block_m + wm * 64 + mi * 16 + g8 + half * 8;
            #pragma unroll
            for (int ni = 0; ni < 4; ni++) {
                const int n0 = block_n + wn * 32 + ni * 8 + 2 * t;
                uint32_t v = packh2(acc[mi][ni][half * 2 + 0],
                                    acc[mi][ni][half * 2 + 1]);
                *reinterpret_cast<uint32_t*>(g_hparth + (long long)m * HID_DIM + n0) = v;
            }
        }
    }
}

// ---------------- 6. gemm_agg: agg@W1l + hparth, relu, project, accumulate -------
__global__ __launch_bounds__(256, 2)
void gemm_agg_kernel(const float* __restrict__ b1,
                     const float* __restrict__ W2l,
                     const float* __restrict__ W2r) {
    extern __shared__ __align__(16) char smem[];
    float (*Wc)[4] = reinterpret_cast<float(*)[4]>(smem + GA_WC);
    float* bias_s = reinterpret_cast<float*>(smem + GA_BIAS);

    const uint32_t sm_base = (uint32_t)__cvta_generic_to_shared(smem);
    const uint32_t as_u = sm_base + GX_A;
    const uint32_t bs_u = sm_base + GX_B;
    const int tid = threadIdx.x;
    const int warp = tid >> 5, lane = tid & 31;
    const int wm = warp >> 2, wn = warp & 3;
    const int g8 = lane >> 2, t = lane & 3;
    const int block_m = blockIdx.y * 128;
    const int block_n = blockIdx.x * 128;

    #pragma unroll
    for (int ph = 0; ph < 2; ph++) {
        const int kb = ph * 64;
        #pragma unroll
        for (int i = 0; i < 4; i++) {
            int id = tid + i * 256;
            int row = id >> 3;
            int ch = (id & 7) * 8;
            cp16(as_u + (row * SROW + kb + ch) * 2,
                 g_aggh + (long long)(block_m + row) * IN_DIM + kb + ch);
        }
        #pragma unroll
        for (int i = 0; i < 4; i++) {
            int id = tid + i * 256;
            int k = id >> 4;
            int nc = (id & 15) * 8;
            cp16(bs_u + ((kb + k) * SROW + nc) * 2,
                 g_Wh + (kb + k) * HID_DIM + block_n + nc);
        }
        asm volatile("cp.async.commit_group;" ::: "memory");
    }

    for (int idx = tid; idx < 128 * 4; idx += 256) {
        int nn = idx >> 2, c = idx & 3;
        int n = block_n + nn;
        Wc[nn][c] = (c < 2) ? W2l[n * 2 + c] : W2r[n * 2 + (c - 2)];
    }
    for (int idx = tid; idx < 128; idx += 256) bias_s[idx] = b1[block_n + idx];

    const uint32_t a_lane = ((wm * 64 + (lane & 15)) * SROW + (lane >> 4) * 8) * 2;
    const uint32_t b_lane = ((lane & 15) * SROW + (lane >> 4) * 8) * 2;

    float acc[4][4][4] = {};
    #pragma unroll
    for (int ph = 0; ph < 2; ph++) {
        if (ph == 0) asm volatile("cp.async.wait_group 1;" ::: "memory");
        else         asm volatile("cp.async.wait_group 0;" ::: "memory");
        __syncthreads();
        #pragma unroll
        for (int ks = 0; ks < 4; ks++) {
            const int kk = ph * 64 + ks * 16;
            uint32_t af[4][4], bf[4][2];
            #pragma unroll
            for (int mi = 0; mi < 4; mi++)
                ldsm_x4(af[mi], as_u + a_lane + (mi * 16 * SROW + kk) * 2);
            #pragma unroll
            for (int ni2 = 0; ni2 < 2; ni2++) {
                uint32_t r[4];
                ldsm_x4t(r, bs_u + b_lane + (kk * SROW + wn * 32 + ni2 * 16) * 2);
                bf[ni2 * 2 + 0][0] = r[0]; bf[ni2 * 2 + 0][1] = r[1];
                bf[ni2 * 2 + 1][0] = r[2]; bf[ni2 * 2 + 1][1] = r[3];
            }
            #pragma unroll
            for (int mi = 0; mi < 4; mi++)
                #pragma unroll
                for (int ni = 0; ni < 4; ni++)
                    mma_f16(acc[mi][ni], af[mi], bf[ni]);
        }
    }

    // epilogue: + hparth(f16) + bias, relu, project, reduce over t-quad, accumulate
    #pragma unroll
    for (int mi = 0; mi < 4; mi++) {
        #pragma unroll
        for (int half = 0; half < 2; half++) {
            const int m = block_m + wm * 64 + mi * 16 + g8 + half * 8;
            float s0 = 0.f, s1 = 0.f, s2 = 0.f, s3 = 0.f;
            #pragma unroll
            for (int ni = 0; ni < 4; ni++) {
                const int nl = wn * 32 + ni * 8 + 2 * t;
                __half2 hh = *reinterpret_cast<const __half2*>(
                    g_hparth + (long long)m * HID_DIM + block_n + nl);
                float2 hp = __half22float2(hh);
                #pragma unroll
                for (int r = 0; r < 2; r++) {
                    float hpv = (r == 0) ? hp.x : hp.y;
                    float hv = fmaxf(acc[mi][ni][half * 2 + r] + hpv + bias_s[nl + r], 0.f);
                    s0 += hv * Wc[nl + r][0];
                    s1 += hv * Wc[nl + r][1];
                    s2 += hv * Wc[nl + r][2];
                    s3 += hv * Wc[nl + r][3];
                }
            }
            #pragma unroll
            for (int off = 1; off <= 2; off <<= 1) {
                s0 += __shfl_xor_sync(0xffffffff, s0, off);
                s1 += __shfl_xor_sync(0xffffffff, s1, off);
                s2 += __shfl_xor_sync(0xffffffff, s2, off);
                s3 += __shfl_xor_sync(0xffffffff, s3, off);
            }
            if (t == 0 && m < N_NODES) {
                atomicAdd(&g_pq[m * 4 + 0], s0);
                atomicAdd(&g_pq[m * 4 + 1], s1);
                atomicAdd(&g_pq[m * 4 + 2], s2);
                atomicAdd(&g_pq[m * 4 + 3], s3);
            }
        }
    }
}

// ---------------- 7. final: gather + log_softmax + reset g_cnt -------------------
__global__ void final_kernel(const float* __restrict__ b2,
                             float* __restrict__ out) {
    int n = blockIdx.x * blockDim.x + threadIdx.x;
    if (n >= N_NODES) return;
    g_cnt[n] = 0;
    const int beg = g_row[n];
    const int end = g_row[n + 1];
    float s0 = 0.f, s1 = 0.f;
    int e = beg;
    for (; e + 1 < end; e += 2) {
        int u = g_csr[e], v = g_csr[e + 1];
        float2 pu = *reinterpret_cast<const float2*>(&g_pq[u * 4]);
        float2 pv = *reinterpret_cast<const float2*>(&g_pq[v * 4]);
        s0 += pu.x + pv.x; s1 += pu.y + pv.y;
    }
    if (e < end) {
        int u = g_csr[e];
        float2 pu = *reinterpret_cast<const float2*>(&g_pq[u * 4]);
        s0 += pu.x; s1 += pu.y;
    }
    const float invd = g_invd[n];
    float o0 = s0 * invd + b2[0] + g_pq[n * 4 + 2];
    float o1 = s1 * invd + b2[1] + g_pq[n * 4 + 3];
    float m = fmaxf(o0, o1);
    float lse = m + logf(expf(o0 - m) + expf(o1 - m));
    out[n * 2 + 0] = o0 - lse;
    out[n * 2 + 1] = o1 - lse;
}

// ---------------- launcher: two-stream fork/join ------------------------------------
extern "C" void kernel_launch(void* const* d_in, const int* in_sizes, int n_in,
                              void* d_out, int out_size) {
    const float* x    = (const float*)d_in[0];
    const float* W1l  = (const float*)d_in[1];
    const float* b1   = (const float*)d_in[2];
    const float* W1r  = (const float*)d_in[3];
    const float* W2l  = (const float*)d_in[4];
    const float* b2   = (const float*)d_in[5];
    const float* W2r  = (const float*)d_in[6];
    const int*   ei   = (const int*)d_in[7];
    float* out = (float*)d_out;

    cudaFuncSetAttribute(gemmx_kernel,
                         cudaFuncAttributeMaxDynamicSharedMemorySize, GX_SMEM);
    cudaFuncSetAttribute(gemm_agg_kernel,
                         cudaFuncAttributeMaxDynamicSharedMemorySize, GA_SMEM);

    cudaStream_t s1;
    cudaStreamCreateWithFlags(&s1, cudaStreamNonBlocking);
    cudaEvent_t ev_prep, ev_gx;
    cudaEventCreateWithFlags(&ev_prep, cudaEventDisableTiming);
    cudaEventCreateWithFlags(&ev_gx, cudaEventDisableTiming);

    // default stream: prep (x/W convert + histogram)
    int prep_threads = N_PAD * IN_DIM / 8;
    prep_kernel<<<(prep_threads + 255) / 256, 256>>>(x, W1l, W1r, ei);
    cudaEventRecord(ev_prep, 0);

    // side stream: gemm_x (x @ W1r) — depends only on prep
    cudaStreamWaitEvent(s1, ev_prep, 0);
    gemmx_kernel<<<4 * N_MTILES, 256, GX_SMEM, s1>>>();
    cudaEventRecord(ev_gx, s1);

    // default stream: CSR chain at full occupancy, concurrent with gemm_x
    scan1_kernel<<<49, 1024>>>();
    scan2_kernel<<<49, 1024>>>();
    reorder_kernel<<<(N_EDGES / 2 + 255) / 256, 256>>>(ei);
    aggregate1_kernel<<<(N_PAD * 16 + 255) / 256, 256>>>();

    // join: gemm_agg needs both aggh (default stream) and hparth (s1)
    cudaStreamWaitEvent(0, ev_gx, 0);
    {
        dim3 grid(HID_DIM / 128, N_MTILES);
        gemm_agg_kernel<<<grid, 256, GA_SMEM>>>(b1, W2l, W2r);
    }
    final_kernel<<<(N_NODES + 255) / 256, 256>>>(b2, out);

    cudaEventDestroy(ev_prep);
    cudaEventDestroy(ev_gx);
    cudaStreamDestroy(s1);
}